// round 2
// baseline (speedup 1.0000x reference)
#include <cuda_runtime.h>
#include <cstdint>

#define NA    57600     // 64*100*9 anchors
#define NLOC  6400      // 64*100
#define FW    100
#define PRE   6000
#define POST  300
#define CAP   8192
#define NBIN  65536
#define NW32  188       // ceil(6016/32) words for removed-bitmap

// Base anchors (ratios 0.5,1,2 x scales 8,16,32), numpy banker's rounding baked in.
__constant__ float c_base[36] = {
  -84.f,  -40.f,  99.f,  55.f,
 -176.f,  -88.f, 191.f, 103.f,
 -360.f, -184.f, 375.f, 199.f,
  -56.f,  -56.f,  71.f,  71.f,
 -120.f, -120.f, 135.f, 135.f,
 -248.f, -248.f, 263.f, 263.f,
  -36.f,  -80.f,  51.f,  95.f,
  -80.f, -168.f,  95.f, 183.f,
 -168.f, -344.f, 183.f, 359.f
};

__device__ float4             g_boxes[NA];   // indexed by reference anchor id
__device__ unsigned           g_keys[NA];    // (a,loc) layout for coalescing
__device__ unsigned           g_hist[NBIN];
__device__ unsigned           g_hist2[NBIN];
__device__ int                g_cnt;
__device__ unsigned           g_B;       // 16-bit threshold bin
__device__ unsigned           g_above;   // count strictly above bin B
__device__ unsigned           g_T32;     // exact 32-bit key threshold
__device__ unsigned long long g_cand[CAP];
__device__ float4             g_top[PRE];

// ---------------------------------------------------------------- init
__global__ void k_init() {
    int i = blockIdx.x * blockDim.x + threadIdx.x;
    int stride = gridDim.x * blockDim.x;
    for (; i < NBIN; i += stride) { g_hist[i] = 0u; g_hist2[i] = 0u; }
    if (blockIdx.x == 0 && threadIdx.x == 0) g_cnt = 0;
}

// ---------------------------------------------------------------- decode + 16-bit histogram
__global__ void k_decode(const float* __restrict__ cls,
                         const float* __restrict__ bbox,
                         const int*   __restrict__ ih,
                         const int*   __restrict__ iw) {
    int t = blockIdx.x * blockDim.x + threadIdx.x;
    if (t >= NA) return;
    int a = t / NLOC, loc = t % NLOC;       // coalesced channel reads
    int y = loc / FW, x = loc % FW;
    int ai = loc * 9 + a;                   // reference anchor index

    float s0 = cls[(2 * a)     * NLOC + loc];
    float s1 = cls[(2 * a + 1) * NLOC + loc];
    float m  = fmaxf(s0, s1);
    float e0 = expf(s0 - m), e1 = expf(s1 - m);
    float score = e1 / (e0 + e1);

    float dx = bbox[(4 * a + 0) * NLOC + loc];
    float dy = bbox[(4 * a + 1) * NLOC + loc];
    float dw = bbox[(4 * a + 2) * NLOC + loc];
    float dh = bbox[(4 * a + 3) * NLOC + loc];

    float sx = (float)(x * 16), sy = (float)(y * 16);
    float ax1 = sx + c_base[a * 4 + 0];
    float ay1 = sy + c_base[a * 4 + 1];
    float ax2 = sx + c_base[a * 4 + 2];
    float ay2 = sy + c_base[a * 4 + 3];

    float w  = ax2 - ax1 + 1.0f;
    float h  = ay2 - ay1 + 1.0f;
    float cx = ax1 + 0.5f * w;
    float cy = ay1 + 0.5f * h;

    float pcx = dx * w + cx;
    float pcy = dy * h + cy;
    float pw  = expf(dw) * w;
    float ph  = expf(dh) * h;

    float W = (float)(iw[0] - 1);
    float H = (float)(ih[0] - 1);
    float x1 = fminf(fmaxf(pcx - 0.5f * pw, 0.f), W);
    float y1 = fminf(fmaxf(pcy - 0.5f * ph, 0.f), H);
    float x2 = fminf(fmaxf(pcx + 0.5f * pw, 0.f), W);
    float y2 = fminf(fmaxf(pcy + 0.5f * ph, 0.f), H);

    bool valid = (x2 - x1 + 1.f >= 16.f) && (y2 - y1 + 1.f >= 16.f);
    float s = valid ? score : -1e30f;

    unsigned u = __float_as_uint(s);
    unsigned key = (u & 0x80000000u) ? ~u : (u | 0x80000000u);

    g_keys[t]   = key;
    g_boxes[ai] = make_float4(x1, y1, x2, y2);
    atomicAdd(&g_hist[key >> 16], 1u);
}

// ---------------------------------------------------------------- threshold bin (high 16 bits)
__global__ void k_thresh() {
    __shared__ unsigned sh[1024];
    int t = threadIdx.x;
    int base = t * 64;
    unsigned c = 0;
    #pragma unroll 8
    for (int b = 0; b < 64; b++) c += g_hist[base + b];
    sh[t] = c;
    __syncthreads();
    for (int off = 1; off < 1024; off <<= 1) {
        unsigned v = (t + off < 1024) ? sh[t + off] : 0u;
        __syncthreads();
        sh[t] += v;
        __syncthreads();
    }
    unsigned suffInc = sh[t];
    unsigned above   = (t < 1023) ? sh[t + 1] : 0u;
    if (above < PRE && suffInc >= PRE) {
        unsigned run = above;
        for (int b = 63; b >= 0; b--) {
            unsigned hb = g_hist[base + b];
            run += hb;
            if (run >= PRE) {
                g_B = (unsigned)(base + b);
                g_above = run - hb;   // strictly above bin B
                break;
            }
        }
    }
}

// ---------------------------------------------------------------- low-16-bit histogram inside bin B
__global__ void k_hist2() {
    int t = blockIdx.x * blockDim.x + threadIdx.x;
    if (t >= NA) return;
    unsigned key = g_keys[t];
    if ((key >> 16) == g_B) atomicAdd(&g_hist2[key & 0xFFFFu], 1u);
}

// ---------------------------------------------------------------- exact 32-bit threshold
__global__ void k_thresh2() {
    __shared__ unsigned sh[1024];
    int t = threadIdx.x;
    unsigned need = PRE - g_above;
    int base = t * 64;
    unsigned c = 0;
    #pragma unroll 8
    for (int b = 0; b < 64; b++) c += g_hist2[base + b];
    sh[t] = c;
    __syncthreads();
    for (int off = 1; off < 1024; off <<= 1) {
        unsigned v = (t + off < 1024) ? sh[t + off] : 0u;
        __syncthreads();
        sh[t] += v;
        __syncthreads();
    }
    unsigned suffInc = sh[t];
    unsigned above   = (t < 1023) ? sh[t + 1] : 0u;
    if (above < need && suffInc >= need) {
        unsigned run = above;
        for (int b = 63; b >= 0; b--) {
            run += g_hist2[base + b];
            if (run >= need) {
                g_T32 = (g_B << 16) | (unsigned)(base + b);
                break;
            }
        }
    }
}

// ---------------------------------------------------------------- compact candidates (>= exact threshold)
__global__ void k_compact() {
    int t = blockIdx.x * blockDim.x + threadIdx.x;
    if (t >= NA) return;
    unsigned key = g_keys[t];
    if (key >= g_T32) {
        int p = atomicAdd(&g_cnt, 1);
        if (p < CAP) {
            int a = t / NLOC, loc = t % NLOC;
            unsigned ai = (unsigned)(loc * 9 + a);
            g_cand[p] = ((unsigned long long)key << 32) | (~ai);
        }
    }
}

// ---------------------------------------------------------------- register-blocked bitonic sort (8192 x u64)
#define CE(x, y, d)                                                     \
    do { if ((r[x] < r[y]) == (d)) {                                    \
            unsigned long long _t = r[x]; r[x] = r[y]; r[y] = _t; } } while (0)

__global__ void k_sort() {
    extern __shared__ unsigned long long s[];
    int t = threadIdx.x;           // 1024 threads
    int cnt = g_cnt; if (cnt > CAP) cnt = CAP;
    for (int i = t; i < CAP; i += 1024)
        s[i] = (i < cnt) ? g_cand[i] : 0ULL;
    __syncthreads();

    int base = t * 8;
    unsigned long long r[8];

    // k = 2, 4, 8 entirely in registers
    {
        #pragma unroll
        for (int m = 0; m < 8; m++) r[m] = s[base + m];
        // k=2, j=1
        CE(0,1,true); CE(2,3,false); CE(4,5,true); CE(6,7,false);
        // k=4, j=2
        CE(0,2,true); CE(1,3,true); CE(4,6,false); CE(5,7,false);
        // k=4, j=1
        CE(0,1,true); CE(2,3,true); CE(4,5,false); CE(6,7,false);
        // k=8 (direction uniform per thread)
        bool d8 = ((base & 8) == 0);
        CE(0,4,d8); CE(1,5,d8); CE(2,6,d8); CE(3,7,d8);
        CE(0,2,d8); CE(1,3,d8); CE(4,6,d8); CE(5,7,d8);
        CE(0,1,d8); CE(2,3,d8); CE(4,5,d8); CE(6,7,d8);
        #pragma unroll
        for (int m = 0; m < 8; m++) s[base + m] = r[m];
    }
    __syncthreads();

    for (int k = 16; k <= CAP; k <<= 1) {
        for (int j = k >> 1; j >= 8; j >>= 1) {
            #pragma unroll
            for (int q = 0; q < 4; q++) {
                int p = t + q * 1024;                       // pair id, < 4096
                int i = ((p & ~(j - 1)) << 1) | (p & (j - 1));
                int l = i | j;
                bool desc = ((i & k) == 0);
                unsigned long long a = s[i], b = s[l];
                if ((a < b) == desc) { s[i] = b; s[l] = a; }
            }
            __syncthreads();
        }
        // j = 4,2,1 in registers (uniform direction since k >= 16)
        bool d = ((base & k) == 0);
        #pragma unroll
        for (int m = 0; m < 8; m++) r[m] = s[base + m];
        CE(0,4,d); CE(1,5,d); CE(2,6,d); CE(3,7,d);
        CE(0,2,d); CE(1,3,d); CE(4,6,d); CE(5,7,d);
        CE(0,1,d); CE(2,3,d); CE(4,5,d); CE(6,7,d);
        #pragma unroll
        for (int m = 0; m < 8; m++) s[base + m] = r[m];
        __syncthreads();
    }

    // gather top-PRE boxes in rank order
    for (int rr = t; rr < PRE; rr += 1024) {
        unsigned idx = ~(unsigned)(s[rr]);
        g_top[rr] = (idx < NA) ? g_boxes[idx]
                               : make_float4(0.f, 0.f, 0.f, 0.f);
    }
}

// ---------------------------------------------------------------- fused on-the-fly NMS (1 block, 1024 thr)
__global__ void k_nms(float* __restrict__ out) {
    extern __shared__ float4 sb[];          // PRE boxes, 96 KB
    __shared__ unsigned rem[NW32];
    __shared__ int s_keep[POST];
    __shared__ int s_next;
    int tid = threadIdx.x;
    int warp = tid >> 5;

    for (int i = tid; i < PRE; i += 1024) sb[i] = g_top[i];
    if (tid < NW32) rem[tid] = 0u;
    if (tid == 0) rem[NW32 - 1] = 0xFFFF0000u;   // indices 6000..6015 invalid
    if (tid < POST) s_keep[tid] = 0;
    __syncthreads();

    int nk = 0, cur = 0;
    while (nk < POST) {
        if (tid == 0) {
            int found = -1;
            int w = cur >> 5;
            unsigned msk = ~rem[w] & (0xFFFFFFFFu << (cur & 31));
            for (;;) {
                if (msk) { found = (w << 5) + __ffs(msk) - 1; break; }
                if (++w >= NW32) break;
                msk = ~rem[w];
            }
            s_next = found;
        }
        __syncthreads();
        int i = s_next;
        if (i < 0) break;
        if (tid == 0) s_keep[nk] = i;
        nk++;

        float4 bi = sb[i];
        float ai = (bi.z - bi.x) * (bi.w - bi.y);
        #pragma unroll
        for (int rr = 0; rr < 6; rr++) {
            int j = rr * 1024 + tid;
            bool sup = false;
            if (j < PRE && j > i) {
                float4 bj = sb[j];
                float aj = (bj.z - bj.x) * (bj.w - bj.y);
                float lx = fmaxf(bi.x, bj.x), ly = fmaxf(bi.y, bj.y);
                float rx = fminf(bi.z, bj.z), ry = fminf(bi.w, bj.w);
                float ww = fmaxf(rx - lx, 0.f), hh = fmaxf(ry - ly, 0.f);
                float inter = ww * hh;
                float iou = inter / (ai + aj - inter);
                sup = (iou > 0.7f);
            }
            unsigned bits = __ballot_sync(0xFFFFFFFFu, sup);
            if ((tid & 31) == 0 && bits) rem[rr * 32 + warp] |= bits;
        }
        cur = i + 1;
        __syncthreads();
    }

    __syncthreads();
    for (int k = tid; k < POST; k += 1024) {
        float4 b = sb[s_keep[k]];
        out[k * 5 + 0] = 0.f;
        out[k * 5 + 1] = b.x;
        out[k * 5 + 2] = b.y;
        out[k * 5 + 3] = b.z;
        out[k * 5 + 4] = b.w;
    }
}

// ---------------------------------------------------------------- launch
extern "C" void kernel_launch(void* const* d_in, const int* in_sizes, int n_in,
                              void* d_out, int out_size) {
    const float* cls  = (const float*)d_in[0];
    const float* bbox = (const float*)d_in[1];
    const int*   ih   = (const int*)d_in[2];
    const int*   iw   = (const int*)d_in[3];
    float* out = (float*)d_out;

    static bool attr_set = false;
    if (!attr_set) {
        cudaFuncSetAttribute(k_sort, cudaFuncAttributeMaxDynamicSharedMemorySize,
                             CAP * (int)sizeof(unsigned long long));
        cudaFuncSetAttribute(k_nms, cudaFuncAttributeMaxDynamicSharedMemorySize,
                             PRE * (int)sizeof(float4));
        attr_set = true;
    }

    k_init  <<<64, 256>>>();
    k_decode<<<(NA + 255) / 256, 256>>>(cls, bbox, ih, iw);
    k_thresh<<<1, 1024>>>();
    k_hist2 <<<(NA + 255) / 256, 256>>>();
    k_thresh2<<<1, 1024>>>();
    k_compact<<<(NA + 255) / 256, 256>>>();
    k_sort  <<<1, 1024, CAP * sizeof(unsigned long long)>>>();
    k_nms   <<<1, 1024, PRE * sizeof(float4)>>>(out);
}

// round 3
// speedup vs baseline: 2.3833x; 2.3833x over previous
#include <cuda_runtime.h>
#include <cstdint>

#define NA    57600     // 64*100*9 anchors
#define NLOC  6400      // 64*100
#define FW    100
#define PRE   6000
#define POST  300
#define NW    94        // ceil(6000/64) u64 words
#define CAP   8192
#define NBIN  65536

// Base anchors (ratios 0.5,1,2 x scales 8,16,32), numpy banker's rounding baked in.
__constant__ float c_base[36] = {
  -84.f,  -40.f,  99.f,  55.f,
 -176.f,  -88.f, 191.f, 103.f,
 -360.f, -184.f, 375.f, 199.f,
  -56.f,  -56.f,  71.f,  71.f,
 -120.f, -120.f, 135.f, 135.f,
 -248.f, -248.f, 263.f, 263.f,
  -36.f,  -80.f,  51.f,  95.f,
  -80.f, -168.f,  95.f, 183.f,
 -168.f, -344.f, 183.f, 359.f
};

__device__ float4             g_boxes[NA];   // indexed by reference anchor id
__device__ unsigned           g_keys[NA];    // (a,loc) layout, coalesced
__device__ unsigned           g_hist[NBIN];
__device__ int                g_cnt;
__device__ unsigned           g_B;           // 16-bit threshold bin
__device__ unsigned long long g_cand[CAP];
__device__ float4             g_top[PRE];
__device__ unsigned long long g_mask[(size_t)PRE * NW];

// ---------------------------------------------------------------- init
__global__ void k_init() {
    int i = blockIdx.x * blockDim.x + threadIdx.x;
    int stride = gridDim.x * blockDim.x;
    for (; i < NBIN; i += stride) g_hist[i] = 0u;
    if (blockIdx.x == 0 && threadIdx.x == 0) g_cnt = 0;
}

// ---------------------------------------------------------------- decode + histogram
__global__ void k_decode(const float* __restrict__ cls,
                         const float* __restrict__ bbox,
                         const int*   __restrict__ ih,
                         const int*   __restrict__ iw) {
    int t = blockIdx.x * blockDim.x + threadIdx.x;
    if (t >= NA) return;
    int a = t / NLOC, loc = t % NLOC;       // coalesced channel reads
    int y = loc / FW, x = loc % FW;
    int ai = loc * 9 + a;                   // reference anchor index

    float s0 = cls[(2 * a)     * NLOC + loc];
    float s1 = cls[(2 * a + 1) * NLOC + loc];
    float m  = fmaxf(s0, s1);
    float e0 = expf(s0 - m), e1 = expf(s1 - m);
    float score = e1 / (e0 + e1);

    float dx = bbox[(4 * a + 0) * NLOC + loc];
    float dy = bbox[(4 * a + 1) * NLOC + loc];
    float dw = bbox[(4 * a + 2) * NLOC + loc];
    float dh = bbox[(4 * a + 3) * NLOC + loc];

    float sx = (float)(x * 16), sy = (float)(y * 16);
    float ax1 = sx + c_base[a * 4 + 0];
    float ay1 = sy + c_base[a * 4 + 1];
    float ax2 = sx + c_base[a * 4 + 2];
    float ay2 = sy + c_base[a * 4 + 3];

    float w  = ax2 - ax1 + 1.0f;
    float h  = ay2 - ay1 + 1.0f;
    float cx = ax1 + 0.5f * w;
    float cy = ay1 + 0.5f * h;

    float pcx = dx * w + cx;
    float pcy = dy * h + cy;
    float pw  = expf(dw) * w;
    float ph  = expf(dh) * h;

    float W = (float)(iw[0] - 1);
    float H = (float)(ih[0] - 1);
    float x1 = fminf(fmaxf(pcx - 0.5f * pw, 0.f), W);
    float y1 = fminf(fmaxf(pcy - 0.5f * ph, 0.f), H);
    float x2 = fminf(fmaxf(pcx + 0.5f * pw, 0.f), W);
    float y2 = fminf(fmaxf(pcy + 0.5f * ph, 0.f), H);

    bool valid = (x2 - x1 + 1.f >= 16.f) && (y2 - y1 + 1.f >= 16.f);
    float s = valid ? score : -1e30f;

    unsigned u = __float_as_uint(s);
    unsigned key = (u & 0x80000000u) ? ~u : (u | 0x80000000u);

    g_keys[t]   = key;
    g_boxes[ai] = make_float4(x1, y1, x2, y2);
    atomicAdd(&g_hist[key >> 16], 1u);
}

// ---------------------------------------------------------------- threshold bin (high 16 bits)
__global__ void k_thresh() {
    __shared__ unsigned sh[1024];
    int t = threadIdx.x;
    int base = t * 64;
    unsigned c = 0;
    #pragma unroll 8
    for (int b = 0; b < 64; b++) c += g_hist[base + b];
    sh[t] = c;
    __syncthreads();
    for (int off = 1; off < 1024; off <<= 1) {
        unsigned v = (t + off < 1024) ? sh[t + off] : 0u;
        __syncthreads();
        sh[t] += v;
        __syncthreads();
    }
    unsigned suffInc = sh[t];
    unsigned above   = (t < 1023) ? sh[t + 1] : 0u;
    if (above < PRE && suffInc >= PRE) {
        unsigned run = above;
        for (int b = 63; b >= 0; b--) {
            run += g_hist[base + b];
            if (run >= PRE) { g_B = (unsigned)(base + b); break; }
        }
    }
}

// ---------------------------------------------------------------- compact candidates (bin >= threshold bin)
__global__ void k_compact() {
    int t = blockIdx.x * blockDim.x + threadIdx.x;
    if (t >= NA) return;
    unsigned key = g_keys[t];
    if ((key >> 16) >= g_B) {
        int p = atomicAdd(&g_cnt, 1);
        if (p < CAP) {
            int a = t / NLOC, loc = t % NLOC;
            unsigned ai = (unsigned)(loc * 9 + a);
            g_cand[p] = ((unsigned long long)key << 32) | (~ai);
        }
    }
}

// ---------------------------------------------------------------- exact rank by all-pairs compare (replaces sort)
__global__ void k_rank() {
    __shared__ unsigned long long tile[256];
    int cnt = g_cnt; if (cnt > CAP) cnt = CAP;
    int p = blockIdx.x * blockDim.x + threadIdx.x;     // 32 x 256 covers CAP
    unsigned long long v = (p < cnt) ? g_cand[p] : 0ULL;
    int rank = 0;
    for (int t0 = 0; t0 < cnt; t0 += 256) {
        int j = t0 + threadIdx.x;
        tile[threadIdx.x] = (j < cnt) ? g_cand[j] : 0ULL;
        __syncthreads();
        int lim = min(256, cnt - t0);
        #pragma unroll 4
        for (int q = 0; q < lim; q++) rank += (tile[q] > v);
        __syncthreads();
    }
    if (p < cnt && rank < PRE) {
        unsigned idx = ~(unsigned)v;                   // low 32 bits hold ~anchor
        g_top[rank] = g_boxes[idx];
    }
}

// ---------------------------------------------------------------- IoU bitmask matrix (parallel)
__global__ void k_mask() {
    __shared__ float4 sb[64];
    int cb = blockIdx.x, rb = blockIdx.y, t = threadIdx.x;
    int i = rb * 64 + t;
    if (cb < rb) {                 // all j < i in this block: word is zero
        if (i < PRE) g_mask[(size_t)i * NW + cb] = 0ULL;
        return;
    }
    int j0 = cb * 64;
    int jg = j0 + t;
    sb[t] = (jg < PRE) ? g_top[jg] : make_float4(0.f, 0.f, 0.f, 0.f);
    __syncthreads();
    if (i >= PRE) return;
    float4 bi = g_top[i];
    float ai = (bi.z - bi.x) * (bi.w - bi.y);
    unsigned long long bits = 0ULL;
    #pragma unroll 4
    for (int b = 0; b < 64; b++) {
        int j = j0 + b;
        float4 bj = sb[b];
        float aj = (bj.z - bj.x) * (bj.w - bj.y);
        float lx = fmaxf(bi.x, bj.x), ly = fmaxf(bi.y, bj.y);
        float rx = fminf(bi.z, bj.z), ry = fminf(bi.w, bj.w);
        float ww = fmaxf(rx - lx, 0.f), hh = fmaxf(ry - ly, 0.f);
        float inter = ww * hh;
        float iou = inter / (ai + aj - inter);
        if (j > i && j < PRE && iou > 0.7f) bits |= 1ULL << b;
    }
    g_mask[(size_t)i * NW + cb] = bits;
}

// ---------------------------------------------------------------- serial NMS reduce: 1 warp, bitmap in registers
__global__ void k_nms(float* __restrict__ out) {
    __shared__ int s_keep[POST];
    int lane = threadIdx.x;        // 32 threads

    // lane owns words w = lane, lane+32, lane+64  (w < 94)
    unsigned long long rem0 = 0ULL, rem1 = 0ULL, rem2 = 0ULL;
    if (lane == 29) rem2 = (~0ULL) << 48;    // word 93: indices 6000..6015 invalid
    if (lane >= 30) rem2 = ~0ULL;            // words 94,95 don't exist

    int nk = 0;
    while (nk < POST) {
        int best = 0x7FFFFFFF;
        {
            unsigned long long f0 = ~rem0;
            if (f0) best = (lane << 6) + __ffsll((long long)f0) - 1;
            if (best == 0x7FFFFFFF) {
                unsigned long long f1 = ~rem1;
                if (f1) best = ((lane + 32) << 6) + __ffsll((long long)f1) - 1;
                if (best == 0x7FFFFFFF) {
                    unsigned long long f2 = ~rem2;
                    if (f2) best = ((lane + 64) << 6) + __ffsll((long long)f2) - 1;
                }
            }
        }
        #pragma unroll
        for (int off = 16; off; off >>= 1)
            best = min(best, __shfl_xor_sync(0xFFFFFFFFu, best, off));
        if (best >= PRE) break;

        if (lane == 0) s_keep[nk] = best;
        nk++;

        const unsigned long long* row = g_mask + (size_t)best * NW;
        unsigned long long r0 = row[lane];
        unsigned long long r1 = (lane + 32 < NW) ? row[lane + 32] : 0ULL;
        unsigned long long r2 = (lane + 64 < NW) ? row[lane + 64] : 0ULL;
        rem0 |= r0; rem1 |= r1; rem2 |= r2;

        // mark chosen index as used
        int w = best >> 6;
        if (lane == (w & 31)) {
            unsigned long long bit = 1ULL << (best & 63);
            if (w < 32)       rem0 |= bit;
            else if (w < 64)  rem1 |= bit;
            else              rem2 |= bit;
        }
    }

    __syncwarp();
    for (int k = nk + lane; k < POST; k += 32) s_keep[k] = 0;
    __syncwarp();
    for (int k = lane; k < POST; k += 32) {
        float4 b = g_top[s_keep[k]];
        out[k * 5 + 0] = 0.f;
        out[k * 5 + 1] = b.x;
        out[k * 5 + 2] = b.y;
        out[k * 5 + 3] = b.z;
        out[k * 5 + 4] = b.w;
    }
}

// ---------------------------------------------------------------- launch
extern "C" void kernel_launch(void* const* d_in, const int* in_sizes, int n_in,
                              void* d_out, int out_size) {
    const float* cls  = (const float*)d_in[0];
    const float* bbox = (const float*)d_in[1];
    const int*   ih   = (const int*)d_in[2];
    const int*   iw   = (const int*)d_in[3];
    float* out = (float*)d_out;

    k_init   <<<64, 256>>>();
    k_decode <<<(NA + 255) / 256, 256>>>(cls, bbox, ih, iw);
    k_thresh <<<1, 1024>>>();
    k_compact<<<(NA + 255) / 256, 256>>>();
    k_rank   <<<CAP / 256, 256>>>();
    k_mask   <<<dim3(NW, NW), 64>>>();
    k_nms    <<<1, 32>>>(out);
}

// round 4
// speedup vs baseline: 3.1719x; 1.3309x over previous
#include <cuda_runtime.h>
#include <cstdint>

#define NA    57600     // 64*100*9 anchors
#define NLOC  6400      // 64*100
#define FW    100
#define PRE   6000
#define POST  300
#define NW    94        // ceil(6000/64) u64 words
#define CAP   8192
#define NBIN  65536
#define FULL  0xFFFFFFFFu

typedef unsigned long long u64;

// Base anchors (ratios 0.5,1,2 x scales 8,16,32), numpy banker's rounding baked in.
__constant__ float c_base[36] = {
  -84.f,  -40.f,  99.f,  55.f,
 -176.f,  -88.f, 191.f, 103.f,
 -360.f, -184.f, 375.f, 199.f,
  -56.f,  -56.f,  71.f,  71.f,
 -120.f, -120.f, 135.f, 135.f,
 -248.f, -248.f, 263.f, 263.f,
  -36.f,  -80.f,  51.f,  95.f,
  -80.f, -168.f,  95.f, 183.f,
 -168.f, -344.f, 183.f, 359.f
};

__device__ float4   g_boxes[NA];   // indexed by reference anchor id
__device__ unsigned g_keys[NA];    // (a,loc) layout, coalesced
__device__ unsigned g_hist[NBIN];
__device__ int      g_cnt;
__device__ unsigned g_B;           // 16-bit threshold bin
__device__ u64      g_cand[CAP];
__device__ float4   g_top[PRE];
__device__ u64      g_mask[(size_t)PRE * NW];

// ---------------------------------------------------------------- init
__global__ void k_init() {
    int i = blockIdx.x * blockDim.x + threadIdx.x;
    int stride = gridDim.x * blockDim.x;
    for (; i < NBIN; i += stride) g_hist[i] = 0u;
    if (blockIdx.x == 0 && threadIdx.x == 0) g_cnt = 0;
}

// ---------------------------------------------------------------- decode + histogram
__global__ void k_decode(const float* __restrict__ cls,
                         const float* __restrict__ bbox,
                         const int*   __restrict__ ih,
                         const int*   __restrict__ iw) {
    int t = blockIdx.x * blockDim.x + threadIdx.x;
    if (t >= NA) return;
    int a = t / NLOC, loc = t % NLOC;       // coalesced channel reads
    int y = loc / FW, x = loc % FW;
    int ai = loc * 9 + a;                   // reference anchor index

    float s0 = cls[(2 * a)     * NLOC + loc];
    float s1 = cls[(2 * a + 1) * NLOC + loc];
    float m  = fmaxf(s0, s1);
    float e0 = expf(s0 - m), e1 = expf(s1 - m);
    float score = e1 / (e0 + e1);

    float dx = bbox[(4 * a + 0) * NLOC + loc];
    float dy = bbox[(4 * a + 1) * NLOC + loc];
    float dw = bbox[(4 * a + 2) * NLOC + loc];
    float dh = bbox[(4 * a + 3) * NLOC + loc];

    float sx = (float)(x * 16), sy = (float)(y * 16);
    float ax1 = sx + c_base[a * 4 + 0];
    float ay1 = sy + c_base[a * 4 + 1];
    float ax2 = sx + c_base[a * 4 + 2];
    float ay2 = sy + c_base[a * 4 + 3];

    float w  = ax2 - ax1 + 1.0f;
    float h  = ay2 - ay1 + 1.0f;
    float cx = ax1 + 0.5f * w;
    float cy = ay1 + 0.5f * h;

    float pcx = dx * w + cx;
    float pcy = dy * h + cy;
    float pw  = expf(dw) * w;
    float ph  = expf(dh) * h;

    float W = (float)(iw[0] - 1);
    float H = (float)(ih[0] - 1);
    float x1 = fminf(fmaxf(pcx - 0.5f * pw, 0.f), W);
    float y1 = fminf(fmaxf(pcy - 0.5f * ph, 0.f), H);
    float x2 = fminf(fmaxf(pcx + 0.5f * pw, 0.f), W);
    float y2 = fminf(fmaxf(pcy + 0.5f * ph, 0.f), H);

    bool valid = (x2 - x1 + 1.f >= 16.f) && (y2 - y1 + 1.f >= 16.f);
    float s = valid ? score : -1e30f;

    unsigned u = __float_as_uint(s);
    unsigned key = (u & 0x80000000u) ? ~u : (u | 0x80000000u);

    g_keys[t]   = key;
    g_boxes[ai] = make_float4(x1, y1, x2, y2);
    atomicAdd(&g_hist[key >> 16], 1u);
}

// ---------------------------------------------------------------- threshold bin (high 16 bits)
__global__ void k_thresh() {
    __shared__ unsigned sh[1024];
    int t = threadIdx.x;
    int base = t * 64;
    unsigned c = 0;
    #pragma unroll 8
    for (int b = 0; b < 64; b++) c += g_hist[base + b];
    sh[t] = c;
    __syncthreads();
    for (int off = 1; off < 1024; off <<= 1) {
        unsigned v = (t + off < 1024) ? sh[t + off] : 0u;
        __syncthreads();
        sh[t] += v;
        __syncthreads();
    }
    unsigned suffInc = sh[t];
    unsigned above   = (t < 1023) ? sh[t + 1] : 0u;
    if (above < PRE && suffInc >= PRE) {
        unsigned run = above;
        for (int b = 63; b >= 0; b--) {
            run += g_hist[base + b];
            if (run >= PRE) { g_B = (unsigned)(base + b); break; }
        }
    }
}

// ---------------------------------------------------------------- compact candidates (bin >= threshold bin)
__global__ void k_compact() {
    int t = blockIdx.x * blockDim.x + threadIdx.x;
    if (t >= NA) return;
    unsigned key = g_keys[t];
    if ((key >> 16) >= g_B) {
        int p = atomicAdd(&g_cnt, 1);
        if (p < CAP) {
            int a = t / NLOC, loc = t % NLOC;
            unsigned ai = (unsigned)(loc * 9 + a);
            g_cand[p] = ((u64)key << 32) | (~ai);
        }
    }
}

// ---------------------------------------------------------------- exact rank by all-pairs compare
__global__ void k_rank() {
    __shared__ u64 tile[256];
    int cnt = g_cnt; if (cnt > CAP) cnt = CAP;
    int p = blockIdx.x * blockDim.x + threadIdx.x;
    u64 v = (p < cnt) ? g_cand[p] : 0ULL;
    int rank = 0;
    for (int t0 = 0; t0 < cnt; t0 += 256) {
        int j = t0 + threadIdx.x;
        tile[threadIdx.x] = (j < cnt) ? g_cand[j] : 0ULL;
        __syncthreads();
        int lim = min(256, cnt - t0);
        #pragma unroll 4
        for (int q = 0; q < lim; q++) rank += (tile[q] > v);
        __syncthreads();
    }
    if (p < cnt && rank < PRE) {
        unsigned idx = ~(unsigned)v;
        g_top[rank] = g_boxes[idx];
    }
}

// ---------------------------------------------------------------- IoU bitmask matrix (parallel)
__global__ void k_mask() {
    __shared__ float4 sb[64];
    int cb = blockIdx.x, rb = blockIdx.y, t = threadIdx.x;
    int i = rb * 64 + t;
    if (cb < rb) {
        if (i < PRE) g_mask[(size_t)i * NW + cb] = 0ULL;
        return;
    }
    int j0 = cb * 64;
    int jg = j0 + t;
    sb[t] = (jg < PRE) ? g_top[jg] : make_float4(0.f, 0.f, 0.f, 0.f);
    __syncthreads();
    if (i >= PRE) return;
    float4 bi = g_top[i];
    float ai = (bi.z - bi.x) * (bi.w - bi.y);
    u64 bits = 0ULL;
    #pragma unroll 4
    for (int b = 0; b < 64; b++) {
        int j = j0 + b;
        float4 bj = sb[b];
        float aj = (bj.z - bj.x) * (bj.w - bj.y);
        float lx = fmaxf(bi.x, bj.x), ly = fmaxf(bi.y, bj.y);
        float rx = fminf(bi.z, bj.z), ry = fminf(bi.w, bj.w);
        float ww = fmaxf(rx - lx, 0.f), hh = fmaxf(ry - ly, 0.f);
        float inter = ww * hh;
        float iou = inter / (ai + aj - inter);
        if (j > i && j < PRE && iou > 0.7f) bits |= 1ULL << b;
    }
    g_mask[(size_t)i * NW + cb] = bits;
}

// ---------------------------------------------------------------- serial NMS reduce: 1 warp, regs bitmap, 4-wide lookahead
__global__ void k_nms(float* __restrict__ out) {
    __shared__ int s_keep[POST];
    int lane = threadIdx.x;        // 32 threads

    // lane owns words: lane, lane+32, lane+64  (valid words < 94)
    u64 rem0 = 0ULL, rem1 = 0ULL, rem2 = 0ULL;
    if (lane == 29) rem2 = (~0ULL) << 48;    // word 93: indices 6000..6015 invalid
    if (lane >= 30) rem2 = ~0ULL;            // words 94,95 don't exist

    int nk = 0;
    while (nk < POST) {
        // ---- find first free word (one ballot + one shfl)
        u64 f0 = ~rem0, f1 = ~rem1, f2 = ~rem2;
        unsigned b0 = __ballot_sync(FULL, f0 != 0ULL);
        unsigned b1 = __ballot_sync(FULL, f1 != 0ULL);
        unsigned b2 = __ballot_sync(FULL, f2 != 0ULL);
        int wsel; u64 wfree;
        if (b0) {
            int src = __ffs(b0) - 1; wsel = src;
            wfree = __shfl_sync(FULL, f0, src);
        } else if (b1) {
            int src = __ffs(b1) - 1; wsel = src + 32;
            wfree = __shfl_sync(FULL, f1, src);
        } else if (b2) {
            int src = __ffs(b2) - 1; wsel = src + 64;
            wfree = __shfl_sync(FULL, f2, src);
        } else break;

        // ---- extract up to 4 lowest free indices (uniform across lanes)
        int j[4];
        u64 tbits = wfree;
        #pragma unroll
        for (int m = 0; m < 4; m++) {
            if (tbits) {
                int b = __ffsll((long long)tbits) - 1;
                j[m] = (wsel << 6) + b;
                tbits &= tbits - 1;
            } else j[m] = PRE;
        }

        // ---- prefetch all candidate rows (independent loads, one latency)
        u64 r0[4], r1[4], r2[4];
        #pragma unroll
        for (int m = 0; m < 4; m++) {
            if (j[m] < PRE) {
                const u64* row = g_mask + (size_t)j[m] * NW;
                r0[m] = row[lane];
                r1[m] = row[lane + 32];
                r2[m] = (lane + 64 < NW) ? row[lane + 64] : 0ULL;
            } else { r0[m] = 0ULL; r1[m] = 0ULL; r2[m] = 0ULL; }
        }

        // ---- decide candidates in ascending order
        #pragma unroll
        for (int m = 0; m < 4; m++) {
            int jm = j[m];
            if (jm >= PRE) break;
            int w = jm >> 6;
            u64 bit = 1ULL << (jm & 63);
            bool own0 = (lane == w);
            bool own1 = (lane == w - 32);
            bool own2 = (lane == w - 64);
            bool supp = (own0 && (rem0 & bit)) || (own1 && (rem1 & bit)) ||
                        (own2 && (rem2 & bit));
            if (__any_sync(FULL, supp)) continue;   // suppressed in this round
            if (lane == 0) s_keep[nk] = jm;
            nk++;
            rem0 |= r0[m]; rem1 |= r1[m]; rem2 |= r2[m];
            if (own0) rem0 |= bit;
            if (own1) rem1 |= bit;
            if (own2) rem2 |= bit;
            if (nk == POST) break;
        }
    }

    __syncwarp();
    for (int k = nk + lane; k < POST; k += 32) s_keep[k] = 0;
    __syncwarp();
    for (int k = lane; k < POST; k += 32) {
        float4 b = g_top[s_keep[k]];
        out[k * 5 + 0] = 0.f;
        out[k * 5 + 1] = b.x;
        out[k * 5 + 2] = b.y;
        out[k * 5 + 3] = b.z;
        out[k * 5 + 4] = b.w;
    }
}

// ---------------------------------------------------------------- launch
extern "C" void kernel_launch(void* const* d_in, const int* in_sizes, int n_in,
                              void* d_out, int out_size) {
    const float* cls  = (const float*)d_in[0];
    const float* bbox = (const float*)d_in[1];
    const int*   ih   = (const int*)d_in[2];
    const int*   iw   = (const int*)d_in[3];
    float* out = (float*)d_out;

    k_init   <<<64, 256>>>();
    k_decode <<<(NA + 255) / 256, 256>>>(cls, bbox, ih, iw);
    k_thresh <<<1, 1024>>>();
    k_compact<<<(NA + 255) / 256, 256>>>();
    k_rank   <<<CAP / 256, 256>>>();
    k_mask   <<<dim3(NW, NW), 64>>>();
    k_nms    <<<1, 32>>>(out);
}

// round 5
// speedup vs baseline: 3.6997x; 1.1664x over previous
#include <cuda_runtime.h>
#include <cstdint>

#define NA    57600     // 64*100*9 anchors
#define NLOC  6400      // 64*100
#define FW    100
#define PRE   6000
#define POST  300
#define NW    94        // ceil(6000/64) u64 words
#define CAP   8192
#define NBIN  65536
#define FULL  0xFFFFFFFFu
#define LOOK  8

typedef unsigned long long u64;

// Base anchors (ratios 0.5,1,2 x scales 8,16,32), numpy banker's rounding baked in.
__constant__ float c_base[36] = {
  -84.f,  -40.f,  99.f,  55.f,
 -176.f,  -88.f, 191.f, 103.f,
 -360.f, -184.f, 375.f, 199.f,
  -56.f,  -56.f,  71.f,  71.f,
 -120.f, -120.f, 135.f, 135.f,
 -248.f, -248.f, 263.f, 263.f,
  -36.f,  -80.f,  51.f,  95.f,
  -80.f, -168.f,  95.f, 183.f,
 -168.f, -344.f, 183.f, 359.f
};

__device__ float4   g_boxes[NA];   // indexed by reference anchor id
__device__ unsigned g_keys[NA];    // (a,loc) layout, coalesced
__device__ unsigned g_hist[NBIN];
__device__ int      g_cnt;
__device__ unsigned g_B;           // 16-bit threshold bin
__device__ u64      g_cand[CAP];
__device__ float4   g_top[PRE];
__device__ u64      g_mask[(size_t)PRE * NW];

// ---------------------------------------------------------------- init
__global__ void k_init() {
    int i = blockIdx.x * blockDim.x + threadIdx.x;
    int stride = gridDim.x * blockDim.x;
    for (; i < NBIN; i += stride) g_hist[i] = 0u;
    if (blockIdx.x == 0 && threadIdx.x == 0) g_cnt = 0;
}

// ---------------------------------------------------------------- decode + histogram
__global__ void k_decode(const float* __restrict__ cls,
                         const float* __restrict__ bbox,
                         const int*   __restrict__ ih,
                         const int*   __restrict__ iw) {
    int t = blockIdx.x * blockDim.x + threadIdx.x;
    if (t >= NA) return;
    int a = t / NLOC, loc = t % NLOC;       // coalesced channel reads
    int y = loc / FW, x = loc % FW;
    int ai = loc * 9 + a;                   // reference anchor index

    float s0 = cls[(2 * a)     * NLOC + loc];
    float s1 = cls[(2 * a + 1) * NLOC + loc];
    float m  = fmaxf(s0, s1);
    float e0 = expf(s0 - m), e1 = expf(s1 - m);
    float score = e1 / (e0 + e1);

    float dx = bbox[(4 * a + 0) * NLOC + loc];
    float dy = bbox[(4 * a + 1) * NLOC + loc];
    float dw = bbox[(4 * a + 2) * NLOC + loc];
    float dh = bbox[(4 * a + 3) * NLOC + loc];

    float sx = (float)(x * 16), sy = (float)(y * 16);
    float ax1 = sx + c_base[a * 4 + 0];
    float ay1 = sy + c_base[a * 4 + 1];
    float ax2 = sx + c_base[a * 4 + 2];
    float ay2 = sy + c_base[a * 4 + 3];

    float w  = ax2 - ax1 + 1.0f;
    float h  = ay2 - ay1 + 1.0f;
    float cx = ax1 + 0.5f * w;
    float cy = ay1 + 0.5f * h;

    float pcx = dx * w + cx;
    float pcy = dy * h + cy;
    float pw  = expf(dw) * w;
    float ph  = expf(dh) * h;

    float W = (float)(iw[0] - 1);
    float H = (float)(ih[0] - 1);
    float x1 = fminf(fmaxf(pcx - 0.5f * pw, 0.f), W);
    float y1 = fminf(fmaxf(pcy - 0.5f * ph, 0.f), H);
    float x2 = fminf(fmaxf(pcx + 0.5f * pw, 0.f), W);
    float y2 = fminf(fmaxf(pcy + 0.5f * ph, 0.f), H);

    bool valid = (x2 - x1 + 1.f >= 16.f) && (y2 - y1 + 1.f >= 16.f);
    float s = valid ? score : -1e30f;

    unsigned u = __float_as_uint(s);
    unsigned key = (u & 0x80000000u) ? ~u : (u | 0x80000000u);

    g_keys[t]   = key;
    g_boxes[ai] = make_float4(x1, y1, x2, y2);
    atomicAdd(&g_hist[key >> 16], 1u);
}

// ---------------------------------------------------------------- threshold bin (high 16 bits), vectorized + shfl scan
__global__ void k_thresh() {
    __shared__ unsigned warpsum[32];
    __shared__ unsigned warpsuf[32];
    int t = threadIdx.x;            // 1024 threads
    int lane = t & 31, warp = t >> 5;

    // thread t owns bins [t*64, t*64+64): 16 x uint4 loads
    const uint4* h4 = (const uint4*)(g_hist) + t * 16;
    unsigned c = 0;
    #pragma unroll
    for (int q = 0; q < 16; q++) {
        uint4 v = h4[q];
        c += v.x + v.y + v.z + v.w;
    }

    // warp inclusive suffix-sum (reverse scan via shfl_down)
    unsigned suf = c;
    #pragma unroll
    for (int off = 1; off < 32; off <<= 1) {
        unsigned v = __shfl_down_sync(FULL, suf, off);
        if (lane + off < 32) suf += v;
    }
    if (lane == 0) warpsum[warp] = suf;   // warp total (suffix from its first lane)
    __syncthreads();
    if (warp == 0) {
        unsigned ws = warpsum[lane];
        unsigned s2 = ws;
        #pragma unroll
        for (int off = 1; off < 32; off <<= 1) {
            unsigned v = __shfl_down_sync(FULL, s2, off);
            if (lane + off < 32) s2 += v;
        }
        warpsuf[lane] = s2 - ws;          // strict suffix of later warps
    }
    __syncthreads();

    unsigned suffInc = suf + warpsuf[warp];           // sum of bins >= t*64
    unsigned above   = suffInc - c;                   // sum of bins >= (t+1)*64
    if (above < PRE && suffInc >= PRE) {
        unsigned run = above;
        int base = t * 64;
        for (int b = 63; b >= 0; b--) {
            run += g_hist[base + b];
            if (run >= PRE) { g_B = (unsigned)(base + b); break; }
        }
    }
}

// ---------------------------------------------------------------- compact candidates (bin >= threshold bin)
__global__ void k_compact() {
    int t = blockIdx.x * blockDim.x + threadIdx.x;
    if (t >= NA) return;
    unsigned key = g_keys[t];
    if ((key >> 16) >= g_B) {
        int p = atomicAdd(&g_cnt, 1);
        if (p < CAP) {
            int a = t / NLOC, loc = t % NLOC;
            unsigned ai = (unsigned)(loc * 9 + a);
            g_cand[p] = ((u64)key << 32) | (~ai);
        }
    }
}

// ---------------------------------------------------------------- exact rank by all-pairs compare
__global__ void k_rank() {
    __shared__ u64 tile[256];
    int cnt = g_cnt; if (cnt > CAP) cnt = CAP;
    int p = blockIdx.x * blockDim.x + threadIdx.x;
    u64 v = (p < cnt) ? g_cand[p] : 0ULL;
    int rank = 0;
    for (int t0 = 0; t0 < cnt; t0 += 256) {
        int j = t0 + threadIdx.x;
        tile[threadIdx.x] = (j < cnt) ? g_cand[j] : 0ULL;
        __syncthreads();
        int lim = min(256, cnt - t0);
        #pragma unroll 4
        for (int q = 0; q < lim; q++) rank += (tile[q] > v);
        __syncthreads();
    }
    if (p < cnt && rank < PRE) {
        unsigned idx = ~(unsigned)v;
        g_top[rank] = g_boxes[idx];
    }
}

// ---------------------------------------------------------------- IoU bitmask matrix (parallel)
__global__ void k_mask() {
    __shared__ float4 sb[64];
    int cb = blockIdx.x, rb = blockIdx.y, t = threadIdx.x;
    int i = rb * 64 + t;
    if (cb < rb) {
        if (i < PRE) g_mask[(size_t)i * NW + cb] = 0ULL;
        return;
    }
    int j0 = cb * 64;
    int jg = j0 + t;
    sb[t] = (jg < PRE) ? g_top[jg] : make_float4(0.f, 0.f, 0.f, 0.f);
    __syncthreads();
    if (i >= PRE) return;
    float4 bi = g_top[i];
    float ai = (bi.z - bi.x) * (bi.w - bi.y);
    u64 bits = 0ULL;
    #pragma unroll 4
    for (int b = 0; b < 64; b++) {
        int j = j0 + b;
        float4 bj = sb[b];
        float aj = (bj.z - bj.x) * (bj.w - bj.y);
        float lx = fmaxf(bi.x, bj.x), ly = fmaxf(bi.y, bj.y);
        float rx = fminf(bi.z, bj.z), ry = fminf(bi.w, bj.w);
        float ww = fmaxf(rx - lx, 0.f), hh = fmaxf(ry - ly, 0.f);
        float inter = ww * hh;
        float iou = inter / (ai + aj - inter);
        if (j > i && j < PRE && iou > 0.7f) bits |= 1ULL << b;
    }
    g_mask[(size_t)i * NW + cb] = bits;
}

// ---------------------------------------------------------------- serial NMS reduce: 1 warp, regs bitmap, 8-wide lookahead
__global__ void k_nms(float* __restrict__ out) {
    __shared__ int s_keep[POST];
    int lane = threadIdx.x;        // 32 threads

    // lane owns words: lane, lane+32, lane+64  (valid words < 94)
    u64 rem0 = 0ULL, rem1 = 0ULL, rem2 = 0ULL;
    if (lane == 29) rem2 = (~0ULL) << 48;    // word 93: indices 6000..6015 invalid
    if (lane >= 30) rem2 = ~0ULL;            // words 94,95 don't exist

    int nk = 0;
    while (nk < POST) {
        // ---- find first free word (one ballot + one shfl)
        u64 f0 = ~rem0, f1 = ~rem1, f2 = ~rem2;
        unsigned b0 = __ballot_sync(FULL, f0 != 0ULL);
        unsigned b1 = __ballot_sync(FULL, f1 != 0ULL);
        unsigned b2 = __ballot_sync(FULL, f2 != 0ULL);
        int wsel; u64 wfree;
        if (b0) {
            int src = __ffs(b0) - 1; wsel = src;
            wfree = __shfl_sync(FULL, f0, src);
        } else if (b1) {
            int src = __ffs(b1) - 1; wsel = src + 32;
            wfree = __shfl_sync(FULL, f1, src);
        } else if (b2) {
            int src = __ffs(b2) - 1; wsel = src + 64;
            wfree = __shfl_sync(FULL, f2, src);
        } else break;

        // ---- extract up to LOOK lowest free indices (uniform across lanes)
        int j[LOOK];
        u64 tbits = wfree;
        #pragma unroll
        for (int m = 0; m < LOOK; m++) {
            if (tbits) {
                int b = __ffsll((long long)tbits) - 1;
                j[m] = (wsel << 6) + b;
                tbits &= tbits - 1;
            } else j[m] = PRE;
        }

        // ---- prefetch all candidate rows (independent loads, one latency)
        u64 r0[LOOK], r1[LOOK], r2[LOOK];
        #pragma unroll
        for (int m = 0; m < LOOK; m++) {
            if (j[m] < PRE) {
                const u64* row = g_mask + (size_t)j[m] * NW;
                r0[m] = row[lane];
                r1[m] = row[lane + 32];
                r2[m] = (lane + 64 < NW) ? row[lane + 64] : 0ULL;
            } else { r0[m] = 0ULL; r1[m] = 0ULL; r2[m] = 0ULL; }
        }

        // ---- decide candidates in ascending order
        #pragma unroll
        for (int m = 0; m < LOOK; m++) {
            int jm = j[m];
            if (jm >= PRE) break;
            int w = jm >> 6;
            u64 bit = 1ULL << (jm & 63);
            bool own0 = (lane == w);
            bool own1 = (lane == w - 32);
            bool own2 = (lane == w - 64);
            bool supp = (own0 && (rem0 & bit)) || (own1 && (rem1 & bit)) ||
                        (own2 && (rem2 & bit));
            if (__any_sync(FULL, supp)) continue;   // suppressed in this round
            if (lane == 0) s_keep[nk] = jm;
            nk++;
            rem0 |= r0[m]; rem1 |= r1[m]; rem2 |= r2[m];
            if (own0) rem0 |= bit;
            if (own1) rem1 |= bit;
            if (own2) rem2 |= bit;
            if (nk == POST) break;
        }
    }

    __syncwarp();
    for (int k = nk + lane; k < POST; k += 32) s_keep[k] = 0;
    __syncwarp();
    for (int k = lane; k < POST; k += 32) {
        float4 b = g_top[s_keep[k]];
        out[k * 5 + 0] = 0.f;
        out[k * 5 + 1] = b.x;
        out[k * 5 + 2] = b.y;
        out[k * 5 + 3] = b.z;
        out[k * 5 + 4] = b.w;
    }
}

// ---------------------------------------------------------------- launch
extern "C" void kernel_launch(void* const* d_in, const int* in_sizes, int n_in,
                              void* d_out, int out_size) {
    const float* cls  = (const float*)d_in[0];
    const float* bbox = (const float*)d_in[1];
    const int*   ih   = (const int*)d_in[2];
    const int*   iw   = (const int*)d_in[3];
    float* out = (float*)d_out;

    k_init   <<<64, 256>>>();
    k_decode <<<(NA + 255) / 256, 256>>>(cls, bbox, ih, iw);
    k_thresh <<<1, 1024>>>();
    k_compact<<<(NA + 255) / 256, 256>>>();
    k_rank   <<<CAP / 256, 256>>>();
    k_mask   <<<dim3(NW, NW), 64>>>();
    k_nms    <<<1, 32>>>(out);
}